// round 11
// baseline (speedup 1.0000x reference)
#include <cuda_runtime.h>
#include <cuda_fp16.h>
#include <math.h>
#include <stdint.h>

#define T      4096
#define DIN    1024
#define DOUT   1024
#define NE     8
#define HID    4096
#define BM     128
#define BN     128
#define BK     64
#define MT     32
#define NTHR   256

// smem stage: A 128x128B (16KB), B 64x256B (16KB)
#define SM_A   0
#define SM_B   16384
#define STG_BYTES 32768
#define NSTAGE 3
#define SMEM_TOT (2048 + NSTAGE * STG_BYTES)   // 100352 -> 2 CTAs/SM

// ---------------------------------------------------------------- helpers
__device__ __forceinline__ uint32_t smem_to_u32(const void* p) {
    uint32_t a;
    asm("{ .reg .u64 t; cvta.to.shared.u64 t, %1; cvt.u32.u64 %0, t; }" : "=r"(a) : "l"(p));
    return a;
}
__device__ __forceinline__ void ldmx4(uint32_t* r, uint32_t addr) {
    asm volatile("ldmatrix.sync.aligned.m8n8.x4.shared.b16 {%0,%1,%2,%3}, [%4];"
                 : "=r"(r[0]), "=r"(r[1]), "=r"(r[2]), "=r"(r[3]) : "r"(addr));
}
__device__ __forceinline__ void ldmx4t(uint32_t* r, uint32_t addr) {
    asm volatile("ldmatrix.sync.aligned.m8n8.x4.trans.shared.b16 {%0,%1,%2,%3}, [%4];"
                 : "=r"(r[0]), "=r"(r[1]), "=r"(r[2]), "=r"(r[3]) : "r"(addr));
}
__device__ __forceinline__ void mma_f16(float* c, const uint32_t* a, uint32_t b0, uint32_t b1) {
    asm volatile("mma.sync.aligned.m16n8k16.row.col.f32.f16.f16.f32 "
                 "{%0,%1,%2,%3}, {%4,%5,%6,%7}, {%8,%9}, {%0,%1,%2,%3};"
                 : "+f"(c[0]), "+f"(c[1]), "+f"(c[2]), "+f"(c[3])
                 : "r"(a[0]), "r"(a[1]), "r"(a[2]), "r"(a[3]), "r"(b0), "r"(b1));
}
__device__ __forceinline__ void cp_async16(uint32_t dst, const void* src, uint32_t sz) {
    asm volatile("cp.async.cg.shared.global [%0], [%1], 16, %2;"
                 :: "r"(dst), "l"(src), "r"(sz));
}
#define CP_COMMIT() asm volatile("cp.async.commit_group;")
#define CP_WAIT(n)  asm volatile("cp.async.wait_group %0;" :: "n"(n))
#define SWZ_A(o)  ((o) ^ (((o) >> 3) & 0x70))   // 128B rows
#define SWZ_B2(o) ((o) ^ (((o) >> 4) & 0x70))   // 256B rows

// ---------------------------------------------------------------- device state
__device__ int   g_count[NE];
__device__ int   g_offset[NE];
__device__ int   g_tokens[NE * T];
__device__ int   g_tok_e[T * 2];
__device__ int   g_tok_pos[T * 2];
__device__ float g_tok_w[T * 2];
__device__ __align__(16) __half g_xh[(size_t)T * DIN];
__device__ __align__(16) __half g_w1[(size_t)NE * DIN * HID];   // native [e][k][n]
__device__ __align__(16) __half g_w2[(size_t)NE * HID * DOUT];  // native [e][k][n]
__device__ __align__(16) __half g_h[(size_t)T * 2 * HID];
__device__ __align__(16) float g_O[(size_t)T * 2 * DOUT];
__device__ float g_wdummy[T * NE];

// ---------------------------------------------------------------- small kernels
__global__ void zero_counts_kernel() {
    if (threadIdx.x < NE) g_count[threadIdx.x] = 0;
}

// fp32 -> fp16 convert, 8 elems/thread (16B stores)
__global__ void conv_kernel(const float* __restrict__ src, __half* __restrict__ dst, int n8) {
    int i = blockIdx.x * blockDim.x + threadIdx.x;
    if (i >= n8) return;
    float4 a = ((const float4*)src)[2 * i];
    float4 b = ((const float4*)src)[2 * i + 1];
    union { unsigned short u[8]; uint4 p; } pk;
    __half h0 = __float2half(a.x), h1 = __float2half(a.y);
    __half h2 = __float2half(a.z), h3 = __float2half(a.w);
    __half h4 = __float2half(b.x), h5 = __float2half(b.y);
    __half h6 = __float2half(b.z), h7 = __float2half(b.w);
    pk.u[0] = *(unsigned short*)&h0; pk.u[1] = *(unsigned short*)&h1;
    pk.u[2] = *(unsigned short*)&h2; pk.u[3] = *(unsigned short*)&h3;
    pk.u[4] = *(unsigned short*)&h4; pk.u[5] = *(unsigned short*)&h5;
    pk.u[6] = *(unsigned short*)&h6; pk.u[7] = *(unsigned short*)&h7;
    ((uint4*)dst)[i] = pk.p;
}

// 512 threads = 16 warps = 16 tokens per block; two-phase bucket assignment.
__global__ __launch_bounds__(512) void gating_kernel(
        const float* __restrict__ x,
        const float* __restrict__ noise,
        const float* __restrict__ gate_w,
        const float* __restrict__ gate_b,
        const float* __restrict__ noise_w,
        const float* __restrict__ noise_b,
        float* __restrict__ w_out) {
    __shared__ int   si0[16], si1[16];
    __shared__ float sw0[16], sw1[16];
    __shared__ int   sp0[16], sp1[16];

    int wid = threadIdx.x >> 5, lane = threadIdx.x & 31;
    int tok = blockIdx.x * 16 + wid;
    const float* xr = x + (size_t)tok * DIN;

    float ag[NE], an[NE];
#pragma unroll
    for (int e = 0; e < NE; e++) { ag[e] = 0.f; an[e] = 0.f; }
    for (int ii = 0; ii < DIN / 32; ii++) {
        int i = ii * 32 + lane;
        float xv = xr[i];
        float4 g0 = *(const float4*)(gate_w + (size_t)i * NE);
        float4 g1 = *(const float4*)(gate_w + (size_t)i * NE + 4);
        float4 n0 = *(const float4*)(noise_w + (size_t)i * NE);
        float4 n1 = *(const float4*)(noise_w + (size_t)i * NE + 4);
        ag[0] = fmaf(xv, g0.x, ag[0]); ag[1] = fmaf(xv, g0.y, ag[1]);
        ag[2] = fmaf(xv, g0.z, ag[2]); ag[3] = fmaf(xv, g0.w, ag[3]);
        ag[4] = fmaf(xv, g1.x, ag[4]); ag[5] = fmaf(xv, g1.y, ag[5]);
        ag[6] = fmaf(xv, g1.z, ag[6]); ag[7] = fmaf(xv, g1.w, ag[7]);
        an[0] = fmaf(xv, n0.x, an[0]); an[1] = fmaf(xv, n0.y, an[1]);
        an[2] = fmaf(xv, n0.z, an[2]); an[3] = fmaf(xv, n0.w, an[3]);
        an[4] = fmaf(xv, n1.x, an[4]); an[5] = fmaf(xv, n1.y, an[5]);
        an[6] = fmaf(xv, n1.z, an[6]); an[7] = fmaf(xv, n1.w, an[7]);
    }
#pragma unroll
    for (int e = 0; e < NE; e++) {
#pragma unroll
        for (int o = 16; o > 0; o >>= 1) {
            ag[e] += __shfl_xor_sync(0xffffffffu, ag[e], o);
            an[e] += __shfl_xor_sync(0xffffffffu, an[e], o);
        }
    }
    if (lane == 0) {
        float l[NE];
#pragma unroll
        for (int e = 0; e < NE; e++) {
            float z = an[e] + noise_b[e];
            float sp = (z > 20.f) ? z : log1pf(expf(z));
            l[e] = ag[e] + gate_b[e] + noise[(size_t)tok * NE + e] * sp;
        }
        int i0 = 0; float v0 = l[0];
#pragma unroll
        for (int e = 1; e < NE; e++) if (l[e] > v0) { v0 = l[e]; i0 = e; }
        int i1 = -1; float v1 = -INFINITY;
#pragma unroll
        for (int e = 0; e < NE; e++) if (e != i0 && l[e] > v1) { v1 = l[e]; i1 = e; }
        float eb = expf(v1 - v0);
        float w0 = 1.f / (1.f + eb);
        float w1 = eb / (1.f + eb);
        float wrow[NE];
#pragma unroll
        for (int e = 0; e < NE; e++) wrow[e] = 0.f;
        wrow[i0] = w0; wrow[i1] = w1;
#pragma unroll
        for (int e = 0; e < NE; e++) w_out[(size_t)tok * NE + e] = wrow[e];
        si0[wid] = i0; si1[wid] = i1; sw0[wid] = w0; sw1[wid] = w1;
    }
    __syncthreads();
    if (threadIdx.x < NE) {
        int e = threadIdx.x;
        int c = 0;
        for (int tk = 0; tk < 16; tk++) {
            if (si0[tk] == e) sp0[tk] = c++;
            if (si1[tk] == e) sp1[tk] = c++;
        }
        if (c > 0) {
            int bse = atomicAdd(&g_count[e], c);
            for (int tk = 0; tk < 16; tk++) {
                int t2 = blockIdx.x * 16 + tk;
                if (si0[tk] == e) {
                    int p = bse + sp0[tk];
                    g_tokens[e * T + p] = t2;
                    g_tok_e[2 * t2] = e; g_tok_pos[2 * t2] = p; g_tok_w[2 * t2] = sw0[tk];
                }
                if (si1[tk] == e) {
                    int p = bse + sp1[tk];
                    g_tokens[e * T + p] = t2;
                    g_tok_e[2 * t2 + 1] = e; g_tok_pos[2 * t2 + 1] = p; g_tok_w[2 * t2 + 1] = sw1[tk];
                }
            }
        }
    }
}

__global__ void offsets_kernel() {
    if (threadIdx.x == 0) {
        int s = 0;
        for (int e = 0; e < NE; e++) { g_offset[e] = s; s += g_count[e]; }
    }
}

// ---------------------------------------------------------------- mma.sync GEMM
// 128x128x64 tiles, 8 warps (2x4 grid, warp tile 64x32), 2 CTAs/SM.
// Single-pass fp16; B native [k][n] via ldmatrix.trans; 3-stage cp.async.
template <int PHASE>
__global__ __launch_bounds__(NTHR, 2) void gemm_mma_kernel(const float* __restrict__ bias) {
    constexpr int KD = (PHASE == 1) ? DIN : HID;
    constexpr int ND = (PHASE == 1) ? HID : DOUT;
    constexpr int NT = ND / BN;
    constexpr int NK = KD / BK;
    constexpr bool GATHER = (PHASE == 1);

    int e = blockIdx.x / NT, nt = blockIdx.x % NT;
    int mt = blockIdx.y;
    int cnt = g_count[e];
    int m0 = mt * BM;
    if (m0 >= cnt) return;
    int n0 = nt * BN;
    int base = g_offset[e];
    size_t arow0 = (size_t)(base + m0);

    extern __shared__ char smem[];
    int* toks = (int*)smem;                    // 128 ints
    float* sbias = (float*)(smem + 1024);      // 128 floats
    uint32_t stgu = smem_to_u32(smem) + 2048;

    int tid = threadIdx.x, wid = tid >> 5, lane = tid & 31;
    int warp_m = wid >> 2, warp_n = wid & 3;

    if (GATHER && tid < BM) {
        int rr = m0 + tid;
        toks[tid] = (rr < cnt) ? g_tokens[e * T + rr] : -1;
    }
    if (tid < BN) sbias[tid] = bias[(size_t)e * ND + n0 + tid];
    __syncthreads();

    const __half* A = (PHASE == 1) ? g_xh : g_h;
    const __half* B = (PHASE == 1) ? g_w1 : g_w2;

    // A: 128 rows x 8 chunks(16B) = 1024 chunks; 256 thr x 4
    int ar = tid >> 1, asub = tid & 1;
    uint32_t aszA;
    const __half* aP;
    {
        bool valid; size_t srow;
        if (GATHER) { int tk = toks[ar]; valid = (tk >= 0); srow = (size_t)(valid ? tk : 0); }
        else        { valid = (m0 + ar) < cnt; srow = arow0 + (valid ? ar : 0); }
        aszA = valid ? 16u : 0u;
        aP = A + srow * KD + asub * 32;
    }
    uint32_t sdA[4];
#pragma unroll
    for (int j = 0; j < 4; j++)
        sdA[j] = SWZ_A((uint32_t)(ar * 128 + (asub * 4 + j) * 16));

    // B: 64 k-rows x 16 chunks = 1024 chunks; 256 thr x 4
    int kb = tid >> 2, bc = tid & 3;
    const __half* bP = B + ((size_t)e * KD + kb) * ND + n0 + bc * 8;
    uint32_t sdB[4];
#pragma unroll
    for (int j = 0; j < 4; j++)
        sdB[j] = SWZ_B2((uint32_t)(kb * 256 + (bc + 4 * j) * 16));

    auto issue = [&](int ck) {
        uint32_t st = stgu + (uint32_t)((ck % NSTAGE) * STG_BYTES);
        size_t koA = (size_t)ck * BK;
        size_t koB = (size_t)ck * BK * ND;
#pragma unroll
        for (int j = 0; j < 4; j++)
            cp_async16(st + SM_A + sdA[j], aP + koA + j * 8, aszA);
#pragma unroll
        for (int j = 0; j < 4; j++)
            cp_async16(st + SM_B + sdB[j], bP + koB + j * 32, 16u);
    };

    float acc[4][4][4];
#pragma unroll
    for (int a = 0; a < 4; a++)
#pragma unroll
        for (int b = 0; b < 4; b++)
#pragma unroll
            for (int r = 0; r < 4; r++) acc[a][b][r] = 0.f;

    issue(0); CP_COMMIT();
    if (NK > 1) { issue(1); } CP_COMMIT();

    for (int ck = 0; ck < NK; ck++) {
        CP_WAIT(1);
        __syncthreads();
        if (ck + 2 < NK) issue(ck + 2);
        CP_COMMIT();

        uint32_t sbase = stgu + (uint32_t)((ck % NSTAGE) * STG_BYTES);
#pragma unroll
        for (int ks = 0; ks < 4; ks++) {
            uint32_t bf[8];
#pragma unroll
            for (int p = 0; p < 2; p++) {
                uint32_t bo = SWZ_B2((uint32_t)((ks * 16 + (lane & 15)) * 256 +
                                                warp_n * 64 + p * 32 + (lane >> 4) * 16));
                ldmx4t(&bf[p * 4], sbase + SM_B + bo);
            }
#pragma unroll
            for (int fm = 0; fm < 4; fm++) {
                uint32_t ao = SWZ_A((uint32_t)((warp_m * 64 + fm * 16 + (lane & 15)) * 128 +
                                               ks * 32 + (lane >> 4) * 16));
                uint32_t af[4];
                ldmx4(af, sbase + SM_A + ao);
#pragma unroll
                for (int fn = 0; fn < 4; fn++)
                    mma_f16(acc[fm][fn], af, bf[fn * 2], bf[fn * 2 + 1]);
            }
        }
    }

    // ---------------- epilogue ----------------
#pragma unroll
    for (int fm = 0; fm < 4; fm++) {
#pragma unroll
        for (int fn = 0; fn < 4; fn++) {
            int col = warp_n * 32 + fn * 8 + (lane & 3) * 2;
            float bv0 = sbias[col], bv1 = sbias[col + 1];
#pragma unroll
            for (int h = 0; h < 2; h++) {
                int row = warp_m * 64 + fm * 16 + (lane >> 2) + h * 8;
                if (m0 + row >= cnt) continue;
                size_t crow = arow0 + row;
                float v0 = acc[fm][fn][h * 2 + 0] + bv0;
                float v1 = acc[fm][fn][h * 2 + 1] + bv1;
                if (PHASE == 1) {
                    v0 = fmaxf(v0, 0.f); v1 = fmaxf(v1, 0.f);
                    __half h0 = __float2half(v0);
                    __half h1 = __float2half(v1);
                    union { unsigned short u[2]; uint32_t w; } pk;
                    pk.u[0] = *(unsigned short*)&h0; pk.u[1] = *(unsigned short*)&h1;
                    *(uint32_t*)(g_h + crow * (size_t)ND + n0 + col) = pk.w;
                } else {
                    float2 v; v.x = v0; v.y = v1;
                    *(float2*)(g_O + crow * (size_t)ND + n0 + col) = v;
                }
            }
        }
    }
}

// ---------------------------------------------------------------- combine
__global__ void combine_kernel(float* __restrict__ out) {
    int t = blockIdx.x;
    int e0 = g_tok_e[2 * t], e1 = g_tok_e[2 * t + 1];
    int r0 = g_offset[e0] + g_tok_pos[2 * t];
    int r1 = g_offset[e1] + g_tok_pos[2 * t + 1];
    float w0 = g_tok_w[2 * t], w1 = g_tok_w[2 * t + 1];
    const float4* a = (const float4*)(g_O + (size_t)r0 * DOUT);
    const float4* b = (const float4*)(g_O + (size_t)r1 * DOUT);
    float4* o = (float4*)(out + (size_t)t * DOUT);
    for (int i = threadIdx.x; i < DOUT / 4; i += blockDim.x) {
        float4 av = a[i], bv = b[i];
        float4 r;
        r.x = w0 * av.x + w1 * bv.x;
        r.y = w0 * av.y + w1 * bv.y;
        r.z = w0 * av.z + w1 * bv.z;
        r.w = w0 * av.w + w1 * bv.w;
        o[i] = r;
    }
}

// ---------------------------------------------------------------- launch
extern "C" void kernel_launch(void* const* d_in, const int* in_sizes, int n_in,
                              void* d_out, int out_size) {
    const float* x       = (const float*)d_in[0];
    const float* noise   = (const float*)d_in[1];
    const float* gate_w  = (const float*)d_in[2];
    const float* gate_b  = (const float*)d_in[3];
    const float* noise_w = (const float*)d_in[4];
    const float* noise_b = (const float*)d_in[5];
    const float* w1      = (const float*)d_in[6];
    const float* b1      = (const float*)d_in[7];
    const float* w2      = (const float*)d_in[8];
    const float* b2      = (const float*)d_in[9];
    float* out = (float*)d_out;

    float* w_out;
    if (out_size >= T * DOUT + T * NE) {
        w_out = out + (size_t)T * DOUT;
    } else {
        cudaGetSymbolAddress((void**)&w_out, g_wdummy);
    }

    cudaFuncSetAttribute(gemm_mma_kernel<1>, cudaFuncAttributeMaxDynamicSharedMemorySize, SMEM_TOT);
    cudaFuncSetAttribute(gemm_mma_kernel<2>, cudaFuncAttributeMaxDynamicSharedMemorySize, SMEM_TOT);

    __half *xh, *w1h, *w2h;
    cudaGetSymbolAddress((void**)&xh, g_xh);
    cudaGetSymbolAddress((void**)&w1h, g_w1);
    cudaGetSymbolAddress((void**)&w2h, g_w2);

    zero_counts_kernel<<<1, 32>>>();
    conv_kernel<<<(T * DIN / 8 + 255) / 256, 256>>>(x, xh, T * DIN / 8);
    conv_kernel<<<(NE * DIN * HID / 8 + 255) / 256, 256>>>(w1, w1h, NE * DIN * HID / 8);
    conv_kernel<<<(NE * HID * DOUT / 8 + 255) / 256, 256>>>(w2, w2h, NE * HID * DOUT / 8);
    gating_kernel<<<T / 16, 512>>>(x, noise, gate_w, gate_b, noise_w, noise_b, w_out);
    offsets_kernel<<<1, 32>>>();
    gemm_mma_kernel<1><<<dim3(NE * (HID / BN), MT), NTHR, SMEM_TOT>>>(b1);
    gemm_mma_kernel<2><<<dim3(NE * (DOUT / BN), MT), NTHR, SMEM_TOT>>>(b2);
    combine_kernel<<<T, 256>>>(out);
}